// round 4
// baseline (speedup 1.0000x reference)
#include <cuda_runtime.h>
#include <cstdint>

#define BQ 32
#define DK 128
#define KTOP 10
#define TILE_R 512
#define KC 32
#define NCHUNK (DK / KC)          // 4
#define THREADS 256
#define NB1 148                   // stage-1 grid (1 CTA/SM wave)

// ---------------- device scratch (no allocations allowed) ----------------
__device__ float g_qn[BQ * DK];
__device__ float g_cand_val[NB1 * BQ * KTOP];
__device__ int   g_cand_idx[NB1 * BQ * KTOP];

// ---------------- helpers ----------------
__device__ __forceinline__ void fma2(unsigned long long& acc,
                                     unsigned long long a,
                                     unsigned long long b) {
    asm volatile("fma.rn.f32x2 %0, %1, %2, %0;" : "+l"(acc) : "l"(a), "l"(b));
}
__device__ __forceinline__ float lo32(unsigned long long v) {
    return __uint_as_float((unsigned)(v & 0xffffffffull));
}
__device__ __forceinline__ float hi32(unsigned long long v) {
    return __uint_as_float((unsigned)(v >> 32));
}
__device__ __forceinline__ void cp_async16(unsigned smem_addr, const void* gptr, bool valid) {
    int sz = valid ? 16 : 0;   // src-size 0 -> zero-fill destination
    asm volatile("cp.async.cg.shared.global [%0], [%1], 16, %2;"
                 :: "r"(smem_addr), "l"(gptr), "r"(sz));
}
__device__ __forceinline__ void cp_commit() {
    asm volatile("cp.async.commit_group;");
}
template <int N>
__device__ __forceinline__ void cp_wait() {
    asm volatile("cp.async.wait_group %0;" :: "n"(N));
}

// better(a, b): larger value wins; ties -> smaller index (matches lax.top_k)
__device__ __forceinline__ bool better(float av, int ai, float bv, int bi) {
    return (av > bv) || (av == bv && ai < bi);
}

// ---------------- kernel 0: normalize queries ----------------
__global__ void qnorm_kernel(const float* __restrict__ q) {
    int w = threadIdx.x >> 5, l = threadIdx.x & 31;
    for (int row = w; row < BQ; row += 8) {
        float4 v = reinterpret_cast<const float4*>(q + row * DK)[l];
        float s = v.x * v.x + v.y * v.y + v.z * v.z + v.w * v.w;
        #pragma unroll
        for (int off = 16; off; off >>= 1) s += __shfl_xor_sync(0xffffffffu, s, off);
        float rn = rsqrtf(s + 1e-12f);
        float4 o = make_float4(v.x * rn, v.y * rn, v.z * rn, v.w * rn);
        reinterpret_cast<float4*>(g_qn + row * DK)[l] = o;
    }
}

// ---------------- stage 1: fused norm + GEMM + block top-k ----------------
// Corpus smem layout per chunk buffer: row stride = KC (32 floats), 8 chunks of
// 4 floats per row, chunk slot XOR-swizzled by (row & 7). 16B-aligned for
// cp.async, conflict-free for LDS.128 reads.
__device__ __forceinline__ void stage_chunk(const float* __restrict__ corpus, int N,
                                            int row0, int c, float* buf) {
    int tid = threadIdx.x;
    unsigned sbase = (unsigned)__cvta_generic_to_shared(buf);
    #pragma unroll
    for (int s = 0; s < (TILE_R * KC / 4) / THREADS; ++s) {   // 16 iters
        int idx = tid + s * THREADS;
        int r = idx >> 3, kq = idx & 7;
        bool valid = (row0 + r) < N;
        const float* g = corpus + (valid ? ((size_t)(row0 + r) * DK + c * KC + kq * 4) : 0);
        unsigned d = sbase + (unsigned)(r * KC + ((kq ^ (r & 7)) << 2)) * 4u;
        cp_async16(d, g, valid);
    }
}

__device__ __forceinline__ void insert_locked(float* tv, int* ti, int* lck,
                                              int q, float v, int gi) {
    float* L = tv + q * KTOP;
    int*   I = ti + q * KTOP;
    while (atomicCAS(&lck[q], 0, 1) != 0) { __nanosleep(32); }
    __threadfence_block();
    if (better(v, gi, L[KTOP - 1], I[KTOP - 1])) {
        int p = KTOP - 1;
        while (p > 0 && better(v, gi, L[p - 1], I[p - 1])) {
            L[p] = L[p - 1]; I[p] = I[p - 1]; --p;
        }
        L[p] = v; I[p] = gi;
    }
    __threadfence_block();
    atomicExch(&lck[q], 0);
}

__global__ void __launch_bounds__(THREADS, 1)
stage1_kernel(const float* __restrict__ corpus, int N) {
    extern __shared__ float smem[];
    float* cbuf = smem;                                 // 2*TILE_R*KC
    float* qs   = cbuf + 2 * TILE_R * KC;               // BQ*DK
    float* rns  = qs + BQ * DK;                         // TILE_R
    float* tv   = rns + TILE_R;                         // BQ*KTOP
    int*   ti   = (int*)(tv + BQ * KTOP);               // BQ*KTOP
    int*   lck  = ti + BQ * KTOP;                       // BQ

    const int tid = threadIdx.x;
    const int qg  = tid >> 6;    // 0..3 (warp-uniform)
    const int rg  = tid & 63;    // 0..63

    for (int i = tid; i < BQ * DK; i += THREADS) qs[i] = g_qn[i];
    for (int i = tid; i < BQ * KTOP; i += THREADS) {   // FULL 320-entry init
        tv[i] = -INFINITY; ti[i] = 0x7fffffff;
    }
    if (tid < BQ) lck[tid] = 0;
    __syncthreads();

    const int ntiles = (N + TILE_R - 1) / TILE_R;
    for (int t = blockIdx.x; t < ntiles; t += gridDim.x) {
        const int row0 = t * TILE_R;

        unsigned long long acc[8][8];   // [q within group][row idx]
        unsigned long long ss[8];
        #pragma unroll
        for (int j = 0; j < 8; ++j)
            #pragma unroll
            for (int i = 0; i < 8; ++i) acc[j][i] = 0ull;
        #pragma unroll
        for (int i = 0; i < 8; ++i) ss[i] = 0ull;

        stage_chunk(corpus, N, row0, 0, cbuf);
        cp_commit();

        for (int c = 0; c < NCHUNK; ++c) {
            float* buf = cbuf + (c & 1) * (TILE_R * KC);
            if (c + 1 < NCHUNK) {
                stage_chunk(corpus, N, row0, c + 1,
                            cbuf + ((c + 1) & 1) * (TILE_R * KC));
                cp_commit();
                cp_wait<1>();
            } else {
                cp_wait<0>();
            }
            __syncthreads();

            const float* qb = qs + (qg * 8) * DK + c * KC;
            #pragma unroll
            for (int kk = 0; kk < KC; kk += 4) {
                unsigned long long q2[8][2];
                #pragma unroll
                for (int j = 0; j < 8; ++j) {
                    ulonglong2 v = *reinterpret_cast<const ulonglong2*>(qb + j * DK + kk);
                    q2[j][0] = v.x; q2[j][1] = v.y;
                }
                #pragma unroll
                for (int i = 0; i < 8; ++i) {
                    int row = rg + 64 * i;
                    const float* cp = buf + row * KC + ((((kk >> 2) ^ (row & 7))) << 2);
                    ulonglong2 cv = *reinterpret_cast<const ulonglong2*>(cp);
                    unsigned long long c0 = cv.x;
                    unsigned long long c1 = cv.y;
                    if (qg == 0) { fma2(ss[i], c0, c0); fma2(ss[i], c1, c1); }
                    #pragma unroll
                    for (int j = 0; j < 8; ++j) {
                        fma2(acc[j][i], c0, q2[j][0]);
                        fma2(acc[j][i], c1, q2[j][1]);
                    }
                }
            }
            __syncthreads();
        }

        // row inverse norms
        if (qg == 0) {
            #pragma unroll
            for (int i = 0; i < 8; ++i) {
                float s = lo32(ss[i]) + hi32(ss[i]);
                rns[rg + 64 * i] = rsqrtf(s + 1e-12f);
            }
        }
        __syncthreads();

        // scores + block top-k
        #pragma unroll
        for (int i = 0; i < 8; ++i) {
            int r = rg + 64 * i;
            int gr = row0 + r;
            if (gr >= N) continue;
            float rn = rns[r];
            #pragma unroll
            for (int j = 0; j < 8; ++j) {
                float v = (lo32(acc[j][i]) + hi32(acc[j][i])) * rn;
                int q = qg * 8 + j;
                if (v > tv[q * KTOP + KTOP - 1]) insert_locked(tv, ti, lck, q, v, gr);
            }
        }
        __syncthreads();
    }

    for (int c = tid; c < BQ * KTOP; c += THREADS) {
        g_cand_val[blockIdx.x * BQ * KTOP + c] = tv[c];
        g_cand_idx[blockIdx.x * BQ * KTOP + c] = ti[c];
    }
}

// ---------------- stage 2: merge candidates, write outputs ----------------
__global__ void __launch_bounds__(256)
finalize_kernel(const float* __restrict__ corpus, float* __restrict__ out,
                int N, int nb) {
    const int q = blockIdx.x;
    const int tid = threadIdx.x;
    __shared__ float sv[256 * KTOP];
    __shared__ int   si[256 * KTOP];
    __shared__ float wbv[8]; __shared__ int wbi[8]; __shared__ int wbp[8];
    __shared__ float selv[KTOP]; __shared__ int seli[KTOP];
    __shared__ float rsel[KTOP];

    float lv[KTOP]; int li[KTOP];
    #pragma unroll
    for (int k = 0; k < KTOP; ++k) { lv[k] = -INFINITY; li[k] = 0x7fffffff; }

    int total = nb * KTOP;
    for (int c = tid; c < total; c += 256) {
        int blk = c / KTOP, k = c % KTOP;
        float v = g_cand_val[blk * (BQ * KTOP) + q * KTOP + k];
        int  ix = g_cand_idx[blk * (BQ * KTOP) + q * KTOP + k];
        if (better(v, ix, lv[KTOP - 1], li[KTOP - 1])) {
            int p = KTOP - 1;
            while (p > 0 && better(v, ix, lv[p - 1], li[p - 1])) {
                lv[p] = lv[p - 1]; li[p] = li[p - 1]; --p;
            }
            lv[p] = v; li[p] = ix;
        }
    }
    #pragma unroll
    for (int k = 0; k < KTOP; ++k) { sv[tid * KTOP + k] = lv[k]; si[tid * KTOP + k] = li[k]; }
    __syncthreads();

    const int w = tid >> 5, l = tid & 31;
    for (int r = 0; r < KTOP; ++r) {
        float bv = -INFINITY; int bi = 0x7fffffff; int bp = -1;
        for (int c = tid; c < 256 * KTOP; c += 256) {
            float v = sv[c]; int ix = si[c];
            if (bp < 0 || better(v, ix, bv, bi)) { bv = v; bi = ix; bp = c; }
        }
        #pragma unroll
        for (int off = 16; off; off >>= 1) {
            float ov = __shfl_xor_sync(0xffffffffu, bv, off);
            int oi = __shfl_xor_sync(0xffffffffu, bi, off);
            int op = __shfl_xor_sync(0xffffffffu, bp, off);
            if (op >= 0 && (bp < 0 || better(ov, oi, bv, bi))) { bv = ov; bi = oi; bp = op; }
        }
        if (l == 0) { wbv[w] = bv; wbi[w] = bi; wbp[w] = bp; }
        __syncthreads();
        if (tid == 0) {
            float fv = wbv[0]; int fi = wbi[0]; int fp = wbp[0];
            for (int ww = 1; ww < 8; ++ww)
                if (wbp[ww] >= 0 && (fp < 0 || better(wbv[ww], wbi[ww], fv, fi))) {
                    fv = wbv[ww]; fi = wbi[ww]; fp = wbp[ww];
                }
            selv[r] = fv; seli[r] = (fi == 0x7fffffff) ? 0 : fi;
            if (fp >= 0) sv[fp] = -INFINITY;
        }
        __syncthreads();
    }

    if (tid < KTOP) {
        out[q * KTOP + tid] = selv[tid];
        out[BQ * KTOP + q * KTOP + tid] = (float)seli[tid];
    }

    // recompute inverse norms for the 10 selected rows
    for (int r = w; r < KTOP; r += 8) {
        int row = seli[r]; if (row < 0 || row >= N) row = 0;
        float4 v = reinterpret_cast<const float4*>(corpus + (size_t)row * DK)[l];
        float s = v.x * v.x + v.y * v.y + v.z * v.z + v.w * v.w;
        #pragma unroll
        for (int off = 16; off; off >>= 1) s += __shfl_xor_sync(0xffffffffu, s, off);
        if (l == 0) rsel[r] = rsqrtf(s + 1e-12f);
    }
    __syncthreads();

    size_t base = (size_t)BQ * KTOP * 2 + (size_t)q * KTOP * DK;
    for (int e = tid; e < KTOP * DK; e += 256) {
        int r = e / DK, d = e % DK;
        int row = seli[r]; if (row < 0 || row >= N) row = 0;
        out[base + e] = corpus[(size_t)row * DK + d] * rsel[r];
    }
}

// ---------------- launch ----------------
extern "C" void kernel_launch(void* const* d_in, const int* in_sizes, int n_in,
                              void* d_out, int out_size) {
    const float* query  = (const float*)d_in[0];
    const float* corpus = (const float*)d_in[1];
    const int N = in_sizes[1] / DK;

    const int smem_bytes =
        (2 * TILE_R * KC + BQ * DK + TILE_R + BQ * KTOP) * 4 +
        (BQ * KTOP + BQ) * 4;
    cudaFuncSetAttribute(stage1_kernel,
                         cudaFuncAttributeMaxDynamicSharedMemorySize, smem_bytes);

    qnorm_kernel<<<1, 256>>>(query);
    stage1_kernel<<<NB1, THREADS, smem_bytes>>>(corpus, N);
    finalize_kernel<<<BQ, 256>>>(corpus, (float*)d_out, N, NB1);
}

// round 5
// speedup vs baseline: 1.0233x; 1.0233x over previous
#include <cuda_runtime.h>
#include <cstdint>

#define BQ 32
#define DK 128
#define KTOP 10
#define TILE_R 512
#define KC 32
#define NCHUNK (DK / KC)          // 4
#define THREADS 256
#define NB1 148                   // stage-1 grid (1 CTA/SM wave)

// ---------------- device scratch (no allocations allowed) ----------------
__device__ float g_qn[BQ * DK];
__device__ float g_cand_val[NB1 * BQ * KTOP];
__device__ int   g_cand_idx[NB1 * BQ * KTOP];

// ---------------- helpers ----------------
__device__ __forceinline__ void fma2(unsigned long long& acc,
                                     unsigned long long a,
                                     unsigned long long b) {
    asm volatile("fma.rn.f32x2 %0, %1, %2, %0;" : "+l"(acc) : "l"(a), "l"(b));
}
__device__ __forceinline__ float lo32(unsigned long long v) {
    return __uint_as_float((unsigned)(v & 0xffffffffull));
}
__device__ __forceinline__ float hi32(unsigned long long v) {
    return __uint_as_float((unsigned)(v >> 32));
}
__device__ __forceinline__ void cp_async16(unsigned smem_addr, const void* gptr, bool valid) {
    int sz = valid ? 16 : 0;   // src-size 0 -> zero-fill destination
    asm volatile("cp.async.cg.shared.global [%0], [%1], 16, %2;"
                 :: "r"(smem_addr), "l"(gptr), "r"(sz));
}
__device__ __forceinline__ void cp_commit() {
    asm volatile("cp.async.commit_group;");
}
template <int N>
__device__ __forceinline__ void cp_wait() {
    asm volatile("cp.async.wait_group %0;" :: "n"(N));
}

// better(a, b): larger value wins; ties -> smaller index (matches lax.top_k)
__device__ __forceinline__ bool better(float av, int ai, float bv, int bi) {
    return (av > bv) || (av == bv && ai < bi);
}

// ---------------- kernel 0: normalize queries ----------------
__global__ void qnorm_kernel(const float* __restrict__ q) {
    int w = threadIdx.x >> 5, l = threadIdx.x & 31;
    for (int row = w; row < BQ; row += 8) {
        float4 v = reinterpret_cast<const float4*>(q + row * DK)[l];
        float s = v.x * v.x + v.y * v.y + v.z * v.z + v.w * v.w;
        #pragma unroll
        for (int off = 16; off; off >>= 1) s += __shfl_xor_sync(0xffffffffu, s, off);
        float rn = rsqrtf(s + 1e-12f);
        float4 o = make_float4(v.x * rn, v.y * rn, v.z * rn, v.w * rn);
        reinterpret_cast<float4*>(g_qn + row * DK)[l] = o;
    }
}

// ---------------- stage 1: fused norm + GEMM + block top-k ----------------
// Corpus smem layout per chunk buffer: row stride = KC (32 floats), 8 chunks of
// 4 floats per row, chunk slot XOR-swizzled by (row & 7). 16B-aligned for
// cp.async, conflict-free for LDS.128 reads.
__device__ __forceinline__ void stage_chunk(const float* __restrict__ corpus, int N,
                                            int row0, int c, float* buf) {
    int tid = threadIdx.x;
    unsigned sbase = (unsigned)__cvta_generic_to_shared(buf);
    #pragma unroll
    for (int s = 0; s < (TILE_R * KC / 4) / THREADS; ++s) {   // 16 iters
        int idx = tid + s * THREADS;
        int r = idx >> 3, kq = idx & 7;
        bool valid = (row0 + r) < N;
        const float* g = corpus + (valid ? ((size_t)(row0 + r) * DK + c * KC + kq * 4) : 0);
        unsigned d = sbase + (unsigned)(r * KC + ((kq ^ (r & 7)) << 2)) * 4u;
        cp_async16(d, g, valid);
    }
}

__device__ __forceinline__ void insert_locked(float* tv, int* ti, int* lck,
                                              int q, float v, int gi) {
    float* L = tv + q * KTOP;
    int*   I = ti + q * KTOP;
    while (atomicCAS(&lck[q], 0, 1) != 0) { __nanosleep(32); }
    __threadfence_block();
    if (better(v, gi, L[KTOP - 1], I[KTOP - 1])) {
        int p = KTOP - 1;
        while (p > 0 && better(v, gi, L[p - 1], I[p - 1])) {
            L[p] = L[p - 1]; I[p] = I[p - 1]; --p;
        }
        L[p] = v; I[p] = gi;
    }
    __threadfence_block();
    atomicExch(&lck[q], 0);
}

__global__ void __launch_bounds__(THREADS, 1)
stage1_kernel(const float* __restrict__ corpus, int N) {
    extern __shared__ float smem[];
    float* cbuf = smem;                                 // 2*TILE_R*KC
    float* qs   = cbuf + 2 * TILE_R * KC;               // BQ*DK
    float* rns  = qs + BQ * DK;                         // TILE_R
    float* tv   = rns + TILE_R;                         // BQ*KTOP
    int*   ti   = (int*)(tv + BQ * KTOP);               // BQ*KTOP
    int*   lck  = ti + BQ * KTOP;                       // BQ

    const int tid = threadIdx.x;
    const int qg  = tid >> 6;    // 0..3 (warp-uniform)
    const int rg  = tid & 63;    // 0..63

    for (int i = tid; i < BQ * DK; i += THREADS) qs[i] = g_qn[i];
    for (int i = tid; i < BQ * KTOP; i += THREADS) {   // FULL 320-entry init
        tv[i] = -INFINITY; ti[i] = 0x7fffffff;
    }
    if (tid < BQ) lck[tid] = 0;
    __syncthreads();

    const int ntiles = (N + TILE_R - 1) / TILE_R;
    for (int t = blockIdx.x; t < ntiles; t += gridDim.x) {
        const int row0 = t * TILE_R;

        unsigned long long acc[8][8];   // [q within group][row idx]
        unsigned long long ss[8];
        #pragma unroll
        for (int j = 0; j < 8; ++j)
            #pragma unroll
            for (int i = 0; i < 8; ++i) acc[j][i] = 0ull;
        #pragma unroll
        for (int i = 0; i < 8; ++i) ss[i] = 0ull;

        stage_chunk(corpus, N, row0, 0, cbuf);
        cp_commit();

        for (int c = 0; c < NCHUNK; ++c) {
            float* buf = cbuf + (c & 1) * (TILE_R * KC);
            if (c + 1 < NCHUNK) {
                stage_chunk(corpus, N, row0, c + 1,
                            cbuf + ((c + 1) & 1) * (TILE_R * KC));
                cp_commit();
                cp_wait<1>();
            } else {
                cp_wait<0>();
            }
            __syncthreads();

            const float* qb = qs + (qg * 8) * DK + c * KC;
            #pragma unroll
            for (int kk = 0; kk < KC; kk += 4) {
                unsigned long long q2[8][2];
                #pragma unroll
                for (int j = 0; j < 8; ++j) {
                    ulonglong2 v = *reinterpret_cast<const ulonglong2*>(qb + j * DK + kk);
                    q2[j][0] = v.x; q2[j][1] = v.y;
                }
                #pragma unroll
                for (int i = 0; i < 8; ++i) {
                    int row = rg + 64 * i;
                    const float* cp = buf + row * KC + ((((kk >> 2) ^ (row & 7))) << 2);
                    ulonglong2 cv = *reinterpret_cast<const ulonglong2*>(cp);
                    unsigned long long c0 = cv.x;
                    unsigned long long c1 = cv.y;
                    if (qg == 0) { fma2(ss[i], c0, c0); fma2(ss[i], c1, c1); }
                    #pragma unroll
                    for (int j = 0; j < 8; ++j) {
                        fma2(acc[j][i], c0, q2[j][0]);
                        fma2(acc[j][i], c1, q2[j][1]);
                    }
                }
            }
            __syncthreads();
        }

        // row inverse norms
        if (qg == 0) {
            #pragma unroll
            for (int i = 0; i < 8; ++i) {
                float s = lo32(ss[i]) + hi32(ss[i]);
                rns[rg + 64 * i] = rsqrtf(s + 1e-12f);
            }
        }
        __syncthreads();

        // scores + block top-k
        #pragma unroll
        for (int i = 0; i < 8; ++i) {
            int r = rg + 64 * i;
            int gr = row0 + r;
            if (gr >= N) continue;
            float rn = rns[r];
            #pragma unroll
            for (int j = 0; j < 8; ++j) {
                float v = (lo32(acc[j][i]) + hi32(acc[j][i])) * rn;
                int q = qg * 8 + j;
                if (v > tv[q * KTOP + KTOP - 1]) insert_locked(tv, ti, lck, q, v, gr);
            }
        }
        __syncthreads();
    }

    for (int c = tid; c < BQ * KTOP; c += THREADS) {
        g_cand_val[blockIdx.x * BQ * KTOP + c] = tv[c];
        g_cand_idx[blockIdx.x * BQ * KTOP + c] = ti[c];
    }
}

// ---------------- stage 2: merge candidates, write outputs ----------------
__global__ void __launch_bounds__(256)
finalize_kernel(const float* __restrict__ corpus, float* __restrict__ out,
                int N, int nb) {
    const int q = blockIdx.x;
    const int tid = threadIdx.x;
    __shared__ float sv[256 * KTOP];
    __shared__ int   si[256 * KTOP];
    __shared__ float wbv[8]; __shared__ int wbi[8]; __shared__ int wbp[8];
    __shared__ float selv[KTOP]; __shared__ int seli[KTOP];
    __shared__ float rsel[KTOP];

    float lv[KTOP]; int li[KTOP];
    #pragma unroll
    for (int k = 0; k < KTOP; ++k) { lv[k] = -INFINITY; li[k] = 0x7fffffff; }

    int total = nb * KTOP;
    for (int c = tid; c < total; c += 256) {
        int blk = c / KTOP, k = c % KTOP;
        float v = g_cand_val[blk * (BQ * KTOP) + q * KTOP + k];
        int  ix = g_cand_idx[blk * (BQ * KTOP) + q * KTOP + k];
        if (better(v, ix, lv[KTOP - 1], li[KTOP - 1])) {
            int p = KTOP - 1;
            while (p > 0 && better(v, ix, lv[p - 1], li[p - 1])) {
                lv[p] = lv[p - 1]; li[p] = li[p - 1]; --p;
            }
            lv[p] = v; li[p] = ix;
        }
    }
    #pragma unroll
    for (int k = 0; k < KTOP; ++k) { sv[tid * KTOP + k] = lv[k]; si[tid * KTOP + k] = li[k]; }
    __syncthreads();

    const int w = tid >> 5, l = tid & 31;
    for (int r = 0; r < KTOP; ++r) {
        float bv = -INFINITY; int bi = 0x7fffffff; int bp = -1;
        for (int c = tid; c < 256 * KTOP; c += 256) {
            float v = sv[c]; int ix = si[c];
            if (bp < 0 || better(v, ix, bv, bi)) { bv = v; bi = ix; bp = c; }
        }
        #pragma unroll
        for (int off = 16; off; off >>= 1) {
            float ov = __shfl_xor_sync(0xffffffffu, bv, off);
            int oi = __shfl_xor_sync(0xffffffffu, bi, off);
            int op = __shfl_xor_sync(0xffffffffu, bp, off);
            if (op >= 0 && (bp < 0 || better(ov, oi, bv, bi))) { bv = ov; bi = oi; bp = op; }
        }
        if (l == 0) { wbv[w] = bv; wbi[w] = bi; wbp[w] = bp; }
        __syncthreads();
        if (tid == 0) {
            float fv = wbv[0]; int fi = wbi[0]; int fp = wbp[0];
            for (int ww = 1; ww < 8; ++ww)
                if (wbp[ww] >= 0 && (fp < 0 || better(wbv[ww], wbi[ww], fv, fi))) {
                    fv = wbv[ww]; fi = wbi[ww]; fp = wbp[ww];
                }
            selv[r] = fv; seli[r] = (fi == 0x7fffffff) ? 0 : fi;
            if (fp >= 0) sv[fp] = -INFINITY;
        }
        __syncthreads();
    }

    if (tid < KTOP) {
        out[q * KTOP + tid] = selv[tid];
        out[BQ * KTOP + q * KTOP + tid] = (float)seli[tid];
    }

    // recompute inverse norms for the 10 selected rows
    for (int r = w; r < KTOP; r += 8) {
        int row = seli[r]; if (row < 0 || row >= N) row = 0;
        float4 v = reinterpret_cast<const float4*>(corpus + (size_t)row * DK)[l];
        float s = v.x * v.x + v.y * v.y + v.z * v.z + v.w * v.w;
        #pragma unroll
        for (int off = 16; off; off >>= 1) s += __shfl_xor_sync(0xffffffffu, s, off);
        if (l == 0) rsel[r] = rsqrtf(s + 1e-12f);
    }
    __syncthreads();

    size_t base = (size_t)BQ * KTOP * 2 + (size_t)q * KTOP * DK;
    for (int e = tid; e < KTOP * DK; e += 256) {
        int r = e / DK, d = e % DK;
        int row = seli[r]; if (row < 0 || row >= N) row = 0;
        out[base + e] = corpus[(size_t)row * DK + d] * rsel[r];
    }
}

// ---------------- launch ----------------
extern "C" void kernel_launch(void* const* d_in, const int* in_sizes, int n_in,
                              void* d_out, int out_size) {
    const float* query  = (const float*)d_in[0];
    const float* corpus = (const float*)d_in[1];
    const int N = in_sizes[1] / DK;

    const int smem_bytes =
        (2 * TILE_R * KC + BQ * DK + TILE_R + BQ * KTOP) * 4 +
        (BQ * KTOP + BQ) * 4;
    cudaFuncSetAttribute(stage1_kernel,
                         cudaFuncAttributeMaxDynamicSharedMemorySize, smem_bytes);

    qnorm_kernel<<<1, 256>>>(query);
    stage1_kernel<<<NB1, THREADS, smem_bytes>>>(corpus, N);
    finalize_kernel<<<BQ, 256>>>(corpus, (float*)d_out, N, NB1);
}

// round 6
// speedup vs baseline: 1.7688x; 1.7284x over previous
#include <cuda_runtime.h>
#include <cstdint>

#define BQ 32
#define DK 128
#define KTOP 10
#define TILE_R 256
#define KC 32
#define NCHUNK (DK / KC)          // 4
#define THREADS 256
#define NB1 148                   // stage-1 grid (1 CTA/SM wave)

// ---------------- device scratch (no allocations allowed) ----------------
__device__ float g_cand_val[NB1 * BQ * KTOP];
__device__ int   g_cand_idx[NB1 * BQ * KTOP];
__device__ float g_dummy;

// ---------------- helpers ----------------
__device__ __forceinline__ void fma2(unsigned long long& acc,
                                     unsigned long long a,
                                     unsigned long long b) {
    // NOT volatile: pure arithmetic, let ptxas schedule/hoist loads freely.
    asm("fma.rn.f32x2 %0, %1, %2, %0;" : "+l"(acc) : "l"(a), "l"(b));
}
__device__ __forceinline__ float lo32(unsigned long long v) {
    return __uint_as_float((unsigned)(v & 0xffffffffull));
}
__device__ __forceinline__ float hi32(unsigned long long v) {
    return __uint_as_float((unsigned)(v >> 32));
}
__device__ __forceinline__ void cp_async16(unsigned smem_addr, const void* gptr, bool valid) {
    int sz = valid ? 16 : 0;   // src-size 0 -> zero-fill destination
    asm volatile("cp.async.cg.shared.global [%0], [%1], 16, %2;"
                 :: "r"(smem_addr), "l"(gptr), "r"(sz));
}
__device__ __forceinline__ void cp_commit() {
    asm volatile("cp.async.commit_group;");
}
template <int N>
__device__ __forceinline__ void cp_wait() {
    asm volatile("cp.async.wait_group %0;" :: "n"(N));
}

// better(a, b): larger value wins; ties -> smaller index (matches lax.top_k)
__device__ __forceinline__ bool better(float av, int ai, float bv, int bi) {
    return (av > bv) || (av == bv && ai < bi);
}

// ---------------- stage 1 ----------------
// Corpus smem chunk buffer: TILE_R rows x KC floats, row stride KC. Each row's
// eight 16B quads XOR-swizzled by (row & 7): 16B-aligned cp.async dsts AND
// conflict-free LDS.128 reads (lanes 0..7 of a phase hit distinct quads).
__device__ __forceinline__ void stage_chunk(const float* __restrict__ corpus, int N,
                                            int row0, int c, float* buf) {
    int tid = threadIdx.x;
    unsigned sbase = (unsigned)__cvta_generic_to_shared(buf);
    #pragma unroll
    for (int s = 0; s < (TILE_R * KC / 4) / THREADS; ++s) {   // 8 iters
        int idx = tid + s * THREADS;
        int r = idx >> 3, kq = idx & 7;
        bool valid = (row0 + r) < N;
        const float* g = corpus + (valid ? ((size_t)(row0 + r) * DK + c * KC + kq * 4) : 0);
        unsigned d = sbase + (unsigned)(r * KC + ((kq ^ (r & 7)) << 2)) * 4u;
        cp_async16(d, g, valid);
    }
}

__device__ __forceinline__ void insert_locked(float* tv, int* ti, int* lck,
                                              int q, float v, int gi) {
    float* L = tv + q * KTOP;
    int*   I = ti + q * KTOP;
    while (atomicCAS(&lck[q], 0, 1) != 0) { __nanosleep(32); }
    __threadfence_block();
    if (better(v, gi, L[KTOP - 1], I[KTOP - 1])) {
        int p = KTOP - 1;
        while (p > 0 && better(v, gi, L[p - 1], I[p - 1])) {
            L[p] = L[p - 1]; I[p] = I[p - 1]; --p;
        }
        L[p] = v; I[p] = gi;
    }
    __threadfence_block();
    atomicExch(&lck[q], 0);
}

__global__ void __launch_bounds__(THREADS, 1)
stage1_kernel(const float* __restrict__ query, const float* __restrict__ corpus, int N) {
    extern __shared__ float smem[];
    float* cbuf = smem;                                 // 2*TILE_R*KC
    float* qs   = cbuf + 2 * TILE_R * KC;               // BQ*DK (normalized queries)
    float* rns  = qs + BQ * DK;                         // TILE_R
    float* tv   = rns + TILE_R;                         // BQ*KTOP
    int*   ti   = (int*)(tv + BQ * KTOP);               // BQ*KTOP
    int*   lck  = ti + BQ * KTOP;                       // BQ

    const int tid  = threadIdx.x;
    const int qg   = tid >> 5;   // warp id = query group (0..7), 4 queries each
    const int lane = tid & 31;

    // --- init top-k state (full 320 entries!) + fused query normalization ---
    for (int i = tid; i < BQ * KTOP; i += THREADS) { tv[i] = -INFINITY; ti[i] = 0x7fffffff; }
    if (tid < BQ) lck[tid] = 0;
    {
        for (int row = qg; row < BQ; row += 8) {
            float4 v = reinterpret_cast<const float4*>(query + row * DK)[lane];
            float s = v.x * v.x + v.y * v.y + v.z * v.z + v.w * v.w;
            #pragma unroll
            for (int off = 16; off; off >>= 1) s += __shfl_xor_sync(0xffffffffu, s, off);
            float rn = rsqrtf(s + 1e-12f);
            float4 o = make_float4(v.x * rn, v.y * rn, v.z * rn, v.w * rn);
            reinterpret_cast<float4*>(qs + row * DK)[lane] = o;
        }
    }

    const int ntiles = (N + TILE_R - 1) / TILE_R;
    int t = blockIdx.x;
    if (t < ntiles) { stage_chunk(corpus, N, t * TILE_R, 0, cbuf); cp_commit(); }
    __syncthreads();

    int g = 0;   // double-buffer parity
    for (; t < ntiles; t += NB1) {
        const int row0 = t * TILE_R;

        unsigned long long acc0[8], acc1[8], acc2[8], acc3[8], ss[8];
        #pragma unroll
        for (int i = 0; i < 8; ++i) {
            acc0[i] = acc1[i] = acc2[i] = acc3[i] = 0ull; ss[i] = 0ull;
        }

        #pragma unroll
        for (int c = 0; c < NCHUNK; ++c) {
            float* buf = cbuf + g * (TILE_R * KC);
            bool has_next = (c < NCHUNK - 1) || (t + NB1 < ntiles);
            if (has_next) {
                int nt = (c < NCHUNK - 1) ? t : t + NB1;
                int nc = (c < NCHUNK - 1) ? c + 1 : 0;
                stage_chunk(corpus, N, nt * TILE_R, nc, cbuf + (g ^ 1) * (TILE_R * KC));
                cp_commit();
                cp_wait<1>();
            } else {
                cp_wait<0>();
            }
            __syncthreads();

            const float* qb = qs + (qg * 4) * DK + c * KC;
            #pragma unroll
            for (int kkc = 0; kkc < 8; ++kkc) {           // 4 k per step
                unsigned long long q2x[4], q2y[4];
                #pragma unroll
                for (int j = 0; j < 4; ++j) {
                    ulonglong2 v = *reinterpret_cast<const ulonglong2*>(qb + j * DK + kkc * 4);
                    q2x[j] = v.x; q2y[j] = v.y;
                }
                unsigned long long c0[8], c1[8];
                #pragma unroll
                for (int i = 0; i < 8; ++i) {
                    int row = lane + 32 * i;
                    const float* cp = buf + row * KC + ((kkc ^ (row & 7)) << 2);
                    ulonglong2 cv = *reinterpret_cast<const ulonglong2*>(cp);
                    c0[i] = cv.x; c1[i] = cv.y;
                }
                if (qg == 0) {
                    #pragma unroll
                    for (int i = 0; i < 8; ++i) { fma2(ss[i], c0[i], c0[i]); fma2(ss[i], c1[i], c1[i]); }
                }
                #pragma unroll
                for (int i = 0; i < 8; ++i) {
                    fma2(acc0[i], c0[i], q2x[0]); fma2(acc0[i], c1[i], q2y[0]);
                    fma2(acc1[i], c0[i], q2x[1]); fma2(acc1[i], c1[i], q2y[1]);
                    fma2(acc2[i], c0[i], q2x[2]); fma2(acc2[i], c1[i], q2y[2]);
                    fma2(acc3[i], c0[i], q2x[3]); fma2(acc3[i], c1[i], q2y[3]);
                }
            }
            __syncthreads();
            g ^= 1;
        }

        // row inverse norms (warp 0 covers all TILE_R rows)
        if (qg == 0) {
            #pragma unroll
            for (int i = 0; i < 8; ++i) {
                float s = lo32(ss[i]) + hi32(ss[i]);
                rns[lane + 32 * i] = rsqrtf(s + 1e-12f);
            }
        }
        __syncthreads();

        // scores + block top-k
        #pragma unroll
        for (int i = 0; i < 8; ++i) {
            int r = lane + 32 * i;
            int gr = row0 + r;
            if (gr >= N) continue;
            float rn = rns[r];
            float v0 = (lo32(acc0[i]) + hi32(acc0[i])) * rn;
            float v1 = (lo32(acc1[i]) + hi32(acc1[i])) * rn;
            float v2 = (lo32(acc2[i]) + hi32(acc2[i])) * rn;
            float v3 = (lo32(acc3[i]) + hi32(acc3[i])) * rn;
            int qb4 = qg * 4;
            if (v0 > tv[(qb4 + 0) * KTOP + KTOP - 1]) insert_locked(tv, ti, lck, qb4 + 0, v0, gr);
            if (v1 > tv[(qb4 + 1) * KTOP + KTOP - 1]) insert_locked(tv, ti, lck, qb4 + 1, v1, gr);
            if (v2 > tv[(qb4 + 2) * KTOP + KTOP - 1]) insert_locked(tv, ti, lck, qb4 + 2, v2, gr);
            if (v3 > tv[(qb4 + 3) * KTOP + KTOP - 1]) insert_locked(tv, ti, lck, qb4 + 3, v3, gr);
        }
        __syncthreads();
    }

    for (int c = tid; c < BQ * KTOP; c += THREADS) {
        g_cand_val[blockIdx.x * BQ * KTOP + c] = tv[c];
        g_cand_idx[blockIdx.x * BQ * KTOP + c] = ti[c];
    }
}

// ---------------- stage 2: merge candidates, write outputs ----------------
__global__ void __launch_bounds__(256)
finalize_kernel(const float* __restrict__ corpus, float* __restrict__ out,
                int N, int nb) {
    const int q = blockIdx.x;
    const int tid = threadIdx.x;
    __shared__ float sv[256 * KTOP];
    __shared__ int   si[256 * KTOP];
    __shared__ float wbv[8]; __shared__ int wbi[8]; __shared__ int wbp[8];
    __shared__ float selv[KTOP]; __shared__ int seli[KTOP];
    __shared__ float rsel[KTOP];

    float lv[KTOP]; int li[KTOP];
    #pragma unroll
    for (int k = 0; k < KTOP; ++k) { lv[k] = -INFINITY; li[k] = 0x7fffffff; }

    int total = nb * KTOP;
    for (int c = tid; c < total; c += 256) {
        int blk = c / KTOP, k = c % KTOP;
        float v = g_cand_val[blk * (BQ * KTOP) + q * KTOP + k];
        int  ix = g_cand_idx[blk * (BQ * KTOP) + q * KTOP + k];
        if (better(v, ix, lv[KTOP - 1], li[KTOP - 1])) {
            int p = KTOP - 1;
            while (p > 0 && better(v, ix, lv[p - 1], li[p - 1])) {
                lv[p] = lv[p - 1]; li[p] = li[p - 1]; --p;
            }
            lv[p] = v; li[p] = ix;
        }
    }
    #pragma unroll
    for (int k = 0; k < KTOP; ++k) { sv[tid * KTOP + k] = lv[k]; si[tid * KTOP + k] = li[k]; }
    __syncthreads();

    const int w = tid >> 5, l = tid & 31;
    for (int r = 0; r < KTOP; ++r) {
        float bv = -INFINITY; int bi = 0x7fffffff; int bp = -1;
        for (int c = tid; c < 256 * KTOP; c += 256) {
            float v = sv[c]; int ix = si[c];
            if (bp < 0 || better(v, ix, bv, bi)) { bv = v; bi = ix; bp = c; }
        }
        #pragma unroll
        for (int off = 16; off; off >>= 1) {
            float ov = __shfl_xor_sync(0xffffffffu, bv, off);
            int oi = __shfl_xor_sync(0xffffffffu, bi, off);
            int op = __shfl_xor_sync(0xffffffffu, bp, off);
            if (op >= 0 && (bp < 0 || better(ov, oi, bv, bi))) { bv = ov; bi = oi; bp = op; }
        }
        if (l == 0) { wbv[w] = bv; wbi[w] = bi; wbp[w] = bp; }
        __syncthreads();
        if (tid == 0) {
            float fv = wbv[0]; int fi = wbi[0]; int fp = wbp[0];
            for (int ww = 1; ww < 8; ++ww)
                if (wbp[ww] >= 0 && (fp < 0 || better(wbv[ww], wbi[ww], fv, fi))) {
                    fv = wbv[ww]; fi = wbi[ww]; fp = wbp[ww];
                }
            selv[r] = fv; seli[r] = (fi == 0x7fffffff) ? 0 : fi;
            if (fp >= 0) sv[fp] = -INFINITY;
        }
        __syncthreads();
    }

    if (tid < KTOP) {
        out[q * KTOP + tid] = selv[tid];
        out[BQ * KTOP + q * KTOP + tid] = (float)seli[tid];
    }

    // recompute inverse norms for the 10 selected rows
    for (int r = w; r < KTOP; r += 8) {
        int row = seli[r]; if (row < 0 || row >= N) row = 0;
        float4 v = reinterpret_cast<const float4*>(corpus + (size_t)row * DK)[l];
        float s = v.x * v.x + v.y * v.y + v.z * v.z + v.w * v.w;
        #pragma unroll
        for (int off = 16; off; off >>= 1) s += __shfl_xor_sync(0xffffffffu, s, off);
        if (l == 0) rsel[r] = rsqrtf(s + 1e-12f);
    }
    __syncthreads();

    size_t base = (size_t)BQ * KTOP * 2 + (size_t)q * KTOP * DK;
    for (int e = tid; e < KTOP * DK; e += 256) {
        int r = e / DK, d = e % DK;
        int row = seli[r]; if (row < 0 || row >= N) row = 0;
        out[base + e] = corpus[(size_t)row * DK + d] * rsel[r];
    }
}

// keeps the per-replay launch count at 3 so ncu -s 5 lands on stage1
__global__ void dummy_kernel() { g_dummy = g_cand_val[0]; }

// ---------------- launch ----------------
extern "C" void kernel_launch(void* const* d_in, const int* in_sizes, int n_in,
                              void* d_out, int out_size) {
    const float* query  = (const float*)d_in[0];
    const float* corpus = (const float*)d_in[1];
    const int N = in_sizes[1] / DK;

    const int smem_bytes =
        (2 * TILE_R * KC + BQ * DK + TILE_R + BQ * KTOP) * 4 +
        (BQ * KTOP + BQ) * 4;
    cudaFuncSetAttribute(stage1_kernel,
                         cudaFuncAttributeMaxDynamicSharedMemorySize, smem_bytes);

    stage1_kernel<<<NB1, THREADS, smem_bytes>>>(query, corpus, N);
    finalize_kernel<<<BQ, 256>>>(corpus, (float*)d_out, N, NB1);
    dummy_kernel<<<1, 1>>>();
}

// round 7
// speedup vs baseline: 3.1640x; 1.7888x over previous
#include <cuda_runtime.h>
#include <cstdint>

#define BQ 32
#define DK 128
#define KTOP 10
#define TILE_R 256
#define KC 32
#define NCHUNK (DK / KC)          // 4
#define THREADS 512
#define NB1 148                   // stage-1 grid (1 CTA/SM wave)

// ---------------- device scratch (no allocations allowed) ----------------
__device__ float g_cand_val[NB1 * BQ * KTOP];
__device__ int   g_cand_idx[NB1 * BQ * KTOP];
__device__ float g_dummy;

// ---------------- helpers ----------------
__device__ __forceinline__ void fma2(unsigned long long& acc,
                                     unsigned long long a,
                                     unsigned long long b) {
    asm("fma.rn.f32x2 %0, %1, %2, %0;" : "+l"(acc) : "l"(a), "l"(b));
}
__device__ __forceinline__ float lo32(unsigned long long v) {
    return __uint_as_float((unsigned)(v & 0xffffffffull));
}
__device__ __forceinline__ float hi32(unsigned long long v) {
    return __uint_as_float((unsigned)(v >> 32));
}
__device__ __forceinline__ void cp_async16(unsigned smem_addr, const void* gptr, bool valid) {
    int sz = valid ? 16 : 0;   // src-size 0 -> zero-fill destination
    asm volatile("cp.async.cg.shared.global [%0], [%1], 16, %2;"
                 :: "r"(smem_addr), "l"(gptr), "r"(sz));
}
__device__ __forceinline__ void cp_commit() {
    asm volatile("cp.async.commit_group;");
}
template <int N>
__device__ __forceinline__ void cp_wait() {
    asm volatile("cp.async.wait_group %0;" :: "n"(N));
}

// better(a, b): larger value wins; ties -> smaller index (matches lax.top_k)
__device__ __forceinline__ bool better(float av, int ai, float bv, int bi) {
    return (av > bv) || (av == bv && ai < bi);
}

// ---------------- stage 1 ----------------
// Corpus smem chunk buffer: TILE_R rows x KC floats, row stride KC. Each row's
// eight 16B quads XOR-swizzled by (row & 7): 16B-aligned cp.async dsts AND
// conflict-free LDS.128 reads (8 consecutive rows per phase -> 8 distinct quads).
__device__ __forceinline__ void stage_chunk(const float* __restrict__ corpus, int N,
                                            int row0, int c, float* buf) {
    int tid = threadIdx.x;
    unsigned sbase = (unsigned)__cvta_generic_to_shared(buf);
    #pragma unroll
    for (int s = 0; s < (TILE_R * KC / 4) / THREADS; ++s) {   // 4 iters
        int idx = tid + s * THREADS;
        int r = idx >> 3, kq = idx & 7;
        bool valid = (row0 + r) < N;
        const float* g = corpus + (valid ? ((size_t)(row0 + r) * DK + c * KC + kq * 4) : 0);
        unsigned d = sbase + (unsigned)(r * KC + ((kq ^ (r & 7)) << 2)) * 4u;
        cp_async16(d, g, valid);
    }
}

__device__ __forceinline__ void insert_locked(float* tv, int* ti, int* lck,
                                              int q, float v, int gi) {
    float* L = tv + q * KTOP;
    int*   I = ti + q * KTOP;
    while (atomicCAS(&lck[q], 0, 1) != 0) { __nanosleep(32); }
    __threadfence_block();
    if (better(v, gi, L[KTOP - 1], I[KTOP - 1])) {
        int p = KTOP - 1;
        while (p > 0 && better(v, gi, L[p - 1], I[p - 1])) {
            L[p] = L[p - 1]; I[p] = I[p - 1]; --p;
        }
        L[p] = v; I[p] = gi;
    }
    __threadfence_block();
    atomicExch(&lck[q], 0);
}

__global__ void __launch_bounds__(THREADS, 1)
stage1_kernel(const float* __restrict__ query, const float* __restrict__ corpus, int N) {
    extern __shared__ float smem[];
    float* cbuf = smem;                                 // 2*TILE_R*KC
    float* qs   = cbuf + 2 * TILE_R * KC;               // BQ*DK (normalized queries)
    float* rns  = qs + BQ * DK;                         // TILE_R
    float* tv   = rns + TILE_R;                         // BQ*KTOP
    int*   ti   = (int*)(tv + BQ * KTOP);               // BQ*KTOP
    int*   lck  = ti + BQ * KTOP;                       // BQ

    const int tid  = threadIdx.x;
    const int w    = tid >> 5;
    const int lane = tid & 31;
    const int qg   = w & 3;      // query group: queries qg*8 .. qg*8+7
    const int rq   = w >> 2;     // row quarter: rows rq*64 .. rq*64+63
    const int row0l = lane + 64 * rq;        // first row this thread handles
    const int row1l = row0l + 32;            // second row

    // --- init top-k state (full 320 entries) + fused query normalization ---
    for (int i = tid; i < BQ * KTOP; i += THREADS) { tv[i] = -INFINITY; ti[i] = 0x7fffffff; }
    if (tid < BQ) lck[tid] = 0;
    for (int row = w; row < BQ; row += 16) {
        float4 v = reinterpret_cast<const float4*>(query + row * DK)[lane];
        float s = v.x * v.x + v.y * v.y + v.z * v.z + v.w * v.w;
        #pragma unroll
        for (int off = 16; off; off >>= 1) s += __shfl_xor_sync(0xffffffffu, s, off);
        float rn = rsqrtf(s + 1e-12f);
        float4 o = make_float4(v.x * rn, v.y * rn, v.z * rn, v.w * rn);
        reinterpret_cast<float4*>(qs + row * DK)[lane] = o;
    }

    const int ntiles = (N + TILE_R - 1) / TILE_R;
    int t = blockIdx.x;
    if (t < ntiles) { stage_chunk(corpus, N, t * TILE_R, 0, cbuf); cp_commit(); }
    __syncthreads();

    int g = 0;   // double-buffer parity
    for (; t < ntiles; t += NB1) {
        const int row0 = t * TILE_R;

        unsigned long long acc0[8], acc1[8], ss0, ss1;
        #pragma unroll
        for (int j = 0; j < 8; ++j) { acc0[j] = 0ull; acc1[j] = 0ull; }
        ss0 = ss1 = 0ull;

        #pragma unroll
        for (int c = 0; c < NCHUNK; ++c) {
            float* buf = cbuf + g * (TILE_R * KC);
            bool has_next = (c < NCHUNK - 1) || (t + NB1 < ntiles);
            if (has_next) {
                int nt = (c < NCHUNK - 1) ? t : t + NB1;
                int nc = (c < NCHUNK - 1) ? c + 1 : 0;
                stage_chunk(corpus, N, nt * TILE_R, nc, cbuf + (g ^ 1) * (TILE_R * KC));
                cp_commit();
                cp_wait<1>();
            } else {
                cp_wait<0>();
            }
            __syncthreads();

            const float* qb = qs + (qg * 8) * DK + c * KC;
            #pragma unroll
            for (int kkc = 0; kkc < 8; ++kkc) {           // 4 k per step
                // corpus: two rows, 16B each, swizzled, conflict-free
                const float* cp0 = buf + row0l * KC + ((kkc ^ (row0l & 7)) << 2);
                const float* cp1 = buf + row1l * KC + ((kkc ^ (row1l & 7)) << 2);
                ulonglong2 cv0 = *reinterpret_cast<const ulonglong2*>(cp0);
                ulonglong2 cv1 = *reinterpret_cast<const ulonglong2*>(cp1);
                // queries: 8 warp-uniform 16B broadcasts
                unsigned long long qx[8], qy[8];
                #pragma unroll
                for (int j = 0; j < 8; ++j) {
                    ulonglong2 v = *reinterpret_cast<const ulonglong2*>(qb + j * DK + kkc * 4);
                    qx[j] = v.x; qy[j] = v.y;
                }
                if (qg == 0) {
                    fma2(ss0, cv0.x, cv0.x); fma2(ss0, cv0.y, cv0.y);
                    fma2(ss1, cv1.x, cv1.x); fma2(ss1, cv1.y, cv1.y);
                }
                #pragma unroll
                for (int j = 0; j < 8; ++j) {
                    fma2(acc0[j], cv0.x, qx[j]); fma2(acc0[j], cv0.y, qy[j]);
                    fma2(acc1[j], cv1.x, qx[j]); fma2(acc1[j], cv1.y, qy[j]);
                }
            }
            __syncthreads();
            g ^= 1;
        }

        // row inverse norms (qg==0 warps cover all 256 rows: 4 rq x 2 rows x 32 lanes)
        if (qg == 0) {
            float s0 = lo32(ss0) + hi32(ss0);
            float s1 = lo32(ss1) + hi32(ss1);
            rns[row0l] = rsqrtf(s0 + 1e-12f);
            rns[row1l] = rsqrtf(s1 + 1e-12f);
        }
        __syncthreads();

        // scores + block top-k
        {
            int gr0 = row0 + row0l, gr1 = row0 + row1l;
            float rn0 = rns[row0l], rn1 = rns[row1l];
            if (gr0 < N) {
                #pragma unroll
                for (int j = 0; j < 8; ++j) {
                    float v = (lo32(acc0[j]) + hi32(acc0[j])) * rn0;
                    int q = qg * 8 + j;
                    if (v > tv[q * KTOP + KTOP - 1]) insert_locked(tv, ti, lck, q, v, gr0);
                }
            }
            if (gr1 < N) {
                #pragma unroll
                for (int j = 0; j < 8; ++j) {
                    float v = (lo32(acc1[j]) + hi32(acc1[j])) * rn1;
                    int q = qg * 8 + j;
                    if (v > tv[q * KTOP + KTOP - 1]) insert_locked(tv, ti, lck, q, v, gr1);
                }
            }
        }
        __syncthreads();
    }

    for (int c = tid; c < BQ * KTOP; c += THREADS) {
        g_cand_val[blockIdx.x * BQ * KTOP + c] = tv[c];
        g_cand_idx[blockIdx.x * BQ * KTOP + c] = ti[c];
    }
}

// ---------------- stage 2: merge candidates, write outputs ----------------
__global__ void __launch_bounds__(256)
finalize_kernel(const float* __restrict__ corpus, float* __restrict__ out,
                int N, int nb) {
    const int q = blockIdx.x;
    const int tid = threadIdx.x;
    __shared__ float sv[256 * KTOP];
    __shared__ int   si[256 * KTOP];
    __shared__ float wbv[8]; __shared__ int wbi[8]; __shared__ int wbp[8];
    __shared__ float selv[KTOP]; __shared__ int seli[KTOP];
    __shared__ float rsel[KTOP];

    float lv[KTOP]; int li[KTOP];
    #pragma unroll
    for (int k = 0; k < KTOP; ++k) { lv[k] = -INFINITY; li[k] = 0x7fffffff; }

    int total = nb * KTOP;
    for (int c = tid; c < total; c += 256) {
        int blk = c / KTOP, k = c % KTOP;
        float v = g_cand_val[blk * (BQ * KTOP) + q * KTOP + k];
        int  ix = g_cand_idx[blk * (BQ * KTOP) + q * KTOP + k];
        if (better(v, ix, lv[KTOP - 1], li[KTOP - 1])) {
            int p = KTOP - 1;
            while (p > 0 && better(v, ix, lv[p - 1], li[p - 1])) {
                lv[p] = lv[p - 1]; li[p] = li[p - 1]; --p;
            }
            lv[p] = v; li[p] = ix;
        }
    }
    #pragma unroll
    for (int k = 0; k < KTOP; ++k) { sv[tid * KTOP + k] = lv[k]; si[tid * KTOP + k] = li[k]; }
    __syncthreads();

    const int w = tid >> 5, l = tid & 31;
    for (int r = 0; r < KTOP; ++r) {
        float bv = -INFINITY; int bi = 0x7fffffff; int bp = -1;
        for (int c = tid; c < 256 * KTOP; c += 256) {
            float v = sv[c]; int ix = si[c];
            if (bp < 0 || better(v, ix, bv, bi)) { bv = v; bi = ix; bp = c; }
        }
        #pragma unroll
        for (int off = 16; off; off >>= 1) {
            float ov = __shfl_xor_sync(0xffffffffu, bv, off);
            int oi = __shfl_xor_sync(0xffffffffu, bi, off);
            int op = __shfl_xor_sync(0xffffffffu, bp, off);
            if (op >= 0 && (bp < 0 || better(ov, oi, bv, bi))) { bv = ov; bi = oi; bp = op; }
        }
        if (l == 0) { wbv[w] = bv; wbi[w] = bi; wbp[w] = bp; }
        __syncthreads();
        if (tid == 0) {
            float fv = wbv[0]; int fi = wbi[0]; int fp = wbp[0];
            for (int ww = 1; ww < 8; ++ww)
                if (wbp[ww] >= 0 && (fp < 0 || better(wbv[ww], wbi[ww], fv, fi))) {
                    fv = wbv[ww]; fi = wbi[ww]; fp = wbp[ww];
                }
            selv[r] = fv; seli[r] = (fi == 0x7fffffff) ? 0 : fi;
            if (fp >= 0) sv[fp] = -INFINITY;
        }
        __syncthreads();
    }

    if (tid < KTOP) {
        out[q * KTOP + tid] = selv[tid];
        out[BQ * KTOP + q * KTOP + tid] = (float)seli[tid];
    }

    // recompute inverse norms for the 10 selected rows
    for (int r = w; r < KTOP; r += 8) {
        int row = seli[r]; if (row < 0 || row >= N) row = 0;
        float4 v = reinterpret_cast<const float4*>(corpus + (size_t)row * DK)[l];
        float s = v.x * v.x + v.y * v.y + v.z * v.z + v.w * v.w;
        #pragma unroll
        for (int off = 16; off; off >>= 1) s += __shfl_xor_sync(0xffffffffu, s, off);
        if (l == 0) rsel[r] = rsqrtf(s + 1e-12f);
    }
    __syncthreads();

    size_t base = (size_t)BQ * KTOP * 2 + (size_t)q * KTOP * DK;
    for (int e = tid; e < KTOP * DK; e += 256) {
        int r = e / DK, d = e % DK;
        int row = seli[r]; if (row < 0 || row >= N) row = 0;
        out[base + e] = corpus[(size_t)row * DK + d] * rsel[r];
    }
}

// keeps the per-replay launch count at 3 so ncu -s 5 lands on stage1
__global__ void dummy_kernel() { g_dummy = g_cand_val[0]; }

// ---------------- launch ----------------
extern "C" void kernel_launch(void* const* d_in, const int* in_sizes, int n_in,
                              void* d_out, int out_size) {
    const float* query  = (const float*)d_in[0];
    const float* corpus = (const float*)d_in[1];
    const int N = in_sizes[1] / DK;

    const int smem_bytes =
        (2 * TILE_R * KC + BQ * DK + TILE_R + BQ * KTOP) * 4 +
        (BQ * KTOP + BQ) * 4;
    cudaFuncSetAttribute(stage1_kernel,
                         cudaFuncAttributeMaxDynamicSharedMemorySize, smem_bytes);

    stage1_kernel<<<NB1, THREADS, smem_bytes>>>(query, corpus, N);
    finalize_kernel<<<BQ, 256>>>(corpus, (float*)d_out, N, NB1);
    dummy_kernel<<<1, 1>>>();
}